// round 5
// baseline (speedup 1.0000x reference)
#include <cuda_runtime.h>
#include <math.h>

#define HH 512
#define WW 512
#define PLANE (512*512)
#define SHAPE_OFF (1*PLANE)
#define SIZE_OFF  (1025*PLANE)
#define HEAT_OFF  (1027*PLANE)
#define NPTS 10
#define MM 128
#define BLKS_PER_HM 64

// per-block partial argmax results; every slot written every run -> no init
__device__ unsigned long long g_partial[NPTS][BLKS_PER_HM];
// per-heatmap arrival counters; self-resetting (last block writes 0 back)
__device__ unsigned int g_count[NPTS];
// per-point meta: {pbase, h, w, 0}
__device__ int4 g_meta[NPTS];

__device__ __forceinline__ unsigned int fkey(float v) {
    unsigned int b = __float_as_uint(v);
    return (b & 0x80000000u) ? ~b : (b | 0x80000000u);
}

__device__ __forceinline__ unsigned long long umax64(unsigned long long a,
                                                     unsigned long long b) {
    return a > b ? a : b;
}

// 640 blocks (64/heatmap) x 256 threads; 16 floats/thread via float4.
// Last-arriving block per heatmap resolves idx + sizes into g_meta.
__global__ void argmax_kernel(const float* __restrict__ feat) {
    __shared__ unsigned long long s[64];
    __shared__ unsigned int s_isLast;

    int hm    = blockIdx.x >> 6;
    int chunk = blockIdx.x & 63;
    const float* heat = feat + HEAT_OFF + (size_t)hm * PLANE;
    int base = chunk * 4096;

    unsigned long long best = 0ULL;
#pragma unroll
    for (int j = 0; j < 4; j++) {
        int e = base + ((j * 256 + threadIdx.x) << 2);
        float4 v = *reinterpret_cast<const float4*>(heat + e);
        float vals[4] = {v.x, v.y, v.z, v.w};
#pragma unroll
        for (int m = 0; m < 4; m++) {
            unsigned long long p =
                ((unsigned long long)fkey(vals[m]) << 32) |
                (unsigned int)(~(unsigned int)(e + m));
            best = umax64(best, p);
        }
    }

#pragma unroll
    for (int off = 16; off > 0; off >>= 1)
        best = umax64(best, __shfl_xor_sync(0xFFFFFFFFu, best, off));

    if ((threadIdx.x & 31) == 0) s[threadIdx.x >> 5] = best;
    __syncthreads();
    if (threadIdx.x < 32) {
        unsigned long long v = (threadIdx.x < 8) ? s[threadIdx.x] : 0ULL;
#pragma unroll
        for (int off = 4; off > 0; off >>= 1)
            v = umax64(v, __shfl_xor_sync(0xFFFFFFFFu, v, off));
        if (threadIdx.x == 0) {
            g_partial[hm][chunk] = v;
            __threadfence();
            unsigned int prev = atomicAdd(&g_count[hm], 1u);
            s_isLast = (prev == BLKS_PER_HM - 1) ? 1u : 0u;
        }
    }
    __syncthreads();
    if (!s_isLast) return;

    // ---- last block: resolve idx + sizes into meta ----
    __threadfence();
    if (threadIdx.x < 64) s[threadIdx.x] = g_partial[hm][threadIdx.x];
    __syncthreads();
    if (threadIdx.x < 32) {
        unsigned long long v = umax64(s[threadIdx.x], s[threadIdx.x + 32]);
#pragma unroll
        for (int off = 16; off > 0; off >>= 1)
            v = umax64(v, __shfl_xor_sync(0xFFFFFFFFu, v, off));
        if (threadIdx.x == 0) {
            int idx = (int)(~(unsigned int)(v & 0xFFFFFFFFu));
            float hv = fabsf(feat[SIZE_OFF + idx]);
            float wv = fabsf(feat[SIZE_OFF + PLANE + idx]);
            int h = min(max((int)hv, 1), MM);
            int w = min(max((int)wv, 1), MM);
            g_meta[hm] = make_int4(idx, h, w, 0);
            g_count[hm] = 0u;   // reset for next graph replay
        }
    }
}

// grid (NPTS, MM): one block per output row, 128 threads = one element each.
// Chain: meta (L2) -> {shape rows || saliency row} in parallel -> interp+store.
__global__ void compute_kernel(const float* __restrict__ feat,
                               float* __restrict__ out) {
    __shared__ float s_r0[32], s_r1[32];

    int pt = blockIdx.x;
    int r  = blockIdx.y;
    int c  = threadIdx.x;

    int4 meta = g_meta[pt];
    int pbase = meta.x;
    int h = meta.y, w = meta.z;
    int py = pbase >> 9;
    int px = pbase & 511;
    float hf = (float)h, wf = (float)w;

    // y-coordinate for this row (uniform over block)
    float sy = ((float)r + 0.5f) * 32.0f / hf - 0.5f;
    sy = fminf(fmaxf(sy, 0.0f), 31.0f);
    int y0 = (int)floorf(sy);
    int y1 = min(y0 + 1, 31);
    float wy = sy - (float)y0;

    // saliency load: depends only on meta -> issue before barrier
    int gr = py - (h >> 1) + r;
    int gc = px - (w >> 1) + c;
    bool valid = (r < h) && (c < w) &&
                 (gr >= 0) && (gr < HH) && (gc >= 0) && (gc < WW);
    float sal = valid ? feat[gr * WW + gc] : 0.0f;

    // shape row gathers: warp0 -> y0 row, warp1 -> y1 row (parallel with sal)
    if (threadIdx.x < 32) {
        s_r0[threadIdx.x] =
            feat[SHAPE_OFF + (size_t)(y0 * 32 + threadIdx.x) * PLANE + pbase];
    } else if (threadIdx.x < 64) {
        int x = threadIdx.x - 32;
        s_r1[x] = feat[SHAPE_OFF + (size_t)(y1 * 32 + x) * PLANE + pbase];
    }
    __syncthreads();

    float sx = ((float)c + 0.5f) * 32.0f / wf - 0.5f;
    sx = fminf(fmaxf(sx, 0.0f), 31.0f);
    int x0 = (int)floorf(sx);
    int x1 = min(x0 + 1, 31);
    float wx = sx - (float)x0;

    float r0v = s_r0[x0] * (1.0f - wy) + s_r1[x0] * wy;
    float r1v = s_r0[x1] * (1.0f - wy) + s_r1[x1] * wy;
    float v = r0v * (1.0f - wx) + r1v * wx;
    float lv = 1.0f / (1.0f + __expf(-v));

    out[(size_t)pt * (MM * MM) + (size_t)r * MM + c] = valid ? lv * sal : 0.0f;
}

extern "C" void kernel_launch(void* const* d_in, const int* in_sizes, int n_in,
                              void* d_out, int out_size) {
    const float* feat = (const float*)d_in[0];
    float* out = (float*)d_out;
    argmax_kernel<<<NPTS * BLKS_PER_HM, 256>>>(feat);
    dim3 g(NPTS, MM);
    compute_kernel<<<g, MM>>>(feat, out);
}

// round 6
// speedup vs baseline: 1.0127x; 1.0127x over previous
#include <cuda_runtime.h>
#include <math.h>

#define HH 512
#define WW 512
#define PLANE (512*512)
#define SHAPE_OFF (1*PLANE)
#define SIZE_OFF  (1025*PLANE)
#define HEAT_OFF  (1027*PLANE)
#define NPTS 10
#define MM 128
#define BLKS_PER_HM 64

__device__ unsigned long long g_partial[NPTS][BLKS_PER_HM];
__device__ unsigned int g_arrive[NPTS];   // self-resetting
__device__ unsigned int g_depart[NPTS];   // self-resetting

__device__ __forceinline__ unsigned int fkey(float v) {
    unsigned int b = __float_as_uint(v);
    return (b & 0x80000000u) ? ~b : (b | 0x80000000u);
}
__device__ __forceinline__ unsigned long long umax64(unsigned long long a,
                                                     unsigned long long b) {
    return a > b ? a : b;
}

// 640 blocks x 256 threads, single wave. Block = (hm, chunk).
// Phase 1: argmax of 16KB chunk -> partial. Per-heatmap spin barrier.
// Phase 2: same block computes output rows [2*chunk, 2*chunk+1] of its point.
__global__ void __launch_bounds__(256) fused_kernel(const float* __restrict__ feat,
                                                    float* __restrict__ out) {
    __shared__ unsigned long long s[64];
    __shared__ float s_v[2][2][32];   // [row-half][y0/y1][x]
    __shared__ int4 s_meta;

    int hm    = blockIdx.x >> 6;
    int chunk = blockIdx.x & 63;
    const float* heat = feat + HEAT_OFF + (size_t)hm * PLANE;
    int base = chunk * 4096;
    int tid = threadIdx.x;

    // ---- phase 1: chunk argmax ----
    unsigned long long best = 0ULL;
#pragma unroll
    for (int j = 0; j < 4; j++) {
        int e = base + ((j * 256 + tid) << 2);
        float4 v = *reinterpret_cast<const float4*>(heat + e);
        float vals[4] = {v.x, v.y, v.z, v.w};
#pragma unroll
        for (int m = 0; m < 4; m++) {
            unsigned long long p =
                ((unsigned long long)fkey(vals[m]) << 32) |
                (unsigned int)(~(unsigned int)(e + m));
            best = umax64(best, p);
        }
    }
#pragma unroll
    for (int off = 16; off > 0; off >>= 1)
        best = umax64(best, __shfl_xor_sync(0xFFFFFFFFu, best, off));
    if ((tid & 31) == 0) s[tid >> 5] = best;
    __syncthreads();
    if (tid < 32) {
        unsigned long long v = (tid < 8) ? s[tid] : 0ULL;
#pragma unroll
        for (int off = 4; off > 0; off >>= 1)
            v = umax64(v, __shfl_xor_sync(0xFFFFFFFFu, v, off));
        if (tid == 0) {
            g_partial[hm][chunk] = v;
            __threadfence();
            atomicAdd(&g_arrive[hm], 1u);
            // spin until all 64 siblings arrived (single wave -> no deadlock)
            while (*(volatile unsigned int*)&g_arrive[hm] < BLKS_PER_HM) { }
            __threadfence();
            // departure: last block resets both counters for next replay
            unsigned int prev = atomicAdd(&g_depart[hm], 1u);
            if (prev == BLKS_PER_HM - 1) {
                g_arrive[hm] = 0u;
                g_depart[hm] = 0u;
            }
        }
    }
    __syncthreads();

    // ---- phase 2: reduce partials, resolve meta ----
    if (tid < 64) s[tid] = g_partial[hm][tid];
    __syncthreads();
    if (tid < 32) {
        unsigned long long v = umax64(s[tid], s[tid + 32]);
#pragma unroll
        for (int off = 16; off > 0; off >>= 1)
            v = umax64(v, __shfl_xor_sync(0xFFFFFFFFu, v, off));
        if (tid == 0) {
            int idx = (int)(~(unsigned int)(v & 0xFFFFFFFFu));
            float hv = fabsf(feat[SIZE_OFF + idx]);
            float wv = fabsf(feat[SIZE_OFF + PLANE + idx]);
            int h = min(max((int)hv, 1), MM);
            int w = min(max((int)wv, 1), MM);
            s_meta = make_int4(idx, h, w, 0);
        }
    }
    __syncthreads();

    int pbase = s_meta.x;
    int h = s_meta.y, w = s_meta.z;
    int py = pbase >> 9;
    int px = pbase & 511;
    float hf = (float)h, wf = (float)w;

    int half = tid >> 7;          // 0 or 1
    int c    = tid & 127;         // column
    int r    = chunk * 2 + half;  // output row

    float sy = ((float)r + 0.5f) * 32.0f / hf - 0.5f;
    sy = fminf(fmaxf(sy, 0.0f), 31.0f);
    int y0 = (int)floorf(sy);
    int y1 = min(y0 + 1, 31);
    float wy = sy - (float)y0;

    // saliency load (independent of shape gathers) issued pre-barrier
    int gr = py - (h >> 1) + r;
    int gc = px - (w >> 1) + c;
    bool valid = (r < h) && (c < w) &&
                 (gr >= 0) && (gr < HH) && (gc >= 0) && (gc < WW);
    float sal = valid ? feat[gr * WW + gc] : 0.0f;

    // shape gathers: each half's first 64 threads fetch its two vec rows
    if (c < 32) {
        s_v[half][0][c] = feat[SHAPE_OFF + (size_t)(y0 * 32 + c) * PLANE + pbase];
    } else if (c < 64) {
        int x = c - 32;
        s_v[half][1][x] = feat[SHAPE_OFF + (size_t)(y1 * 32 + x) * PLANE + pbase];
    }
    __syncthreads();

    float sx = ((float)c + 0.5f) * 32.0f / wf - 0.5f;
    sx = fminf(fmaxf(sx, 0.0f), 31.0f);
    int x0 = (int)floorf(sx);
    int x1 = min(x0 + 1, 31);
    float wx = sx - (float)x0;

    float a0 = s_v[half][0][x0] * (1.0f - wy) + s_v[half][1][x0] * wy;
    float a1 = s_v[half][0][x1] * (1.0f - wy) + s_v[half][1][x1] * wy;
    float v = a0 * (1.0f - wx) + a1 * wx;
    float lv = 1.0f / (1.0f + __expf(-v));

    out[(size_t)hm * (MM * MM) + (size_t)r * MM + c] = valid ? lv * sal : 0.0f;
}

extern "C" void kernel_launch(void* const* d_in, const int* in_sizes, int n_in,
                              void* d_out, int out_size) {
    const float* feat = (const float*)d_in[0];
    float* out = (float*)d_out;
    fused_kernel<<<NPTS * BLKS_PER_HM, 256>>>(feat, out);
}

// round 7
// speedup vs baseline: 1.4632x; 1.4449x over previous
#include <cuda_runtime.h>
#include <math.h>

#define HH 512
#define WW 512
#define PLANE (512*512)
#define SHAPE_OFF (1*PLANE)
#define SIZE_OFF  (1025*PLANE)
#define HEAT_OFF  (1027*PLANE)
#define NPTS 10
#define MM 128
#define BLKS_PER_HM 32

// per-block partial argmax results; every slot written every run -> no init
__device__ unsigned long long g_partial[NPTS][BLKS_PER_HM];

__device__ __forceinline__ unsigned int fkey(float v) {
    unsigned int b = __float_as_uint(v);
    return (b & 0x80000000u) ? ~b : (b | 0x80000000u);
}
__device__ __forceinline__ unsigned long long umax64(unsigned long long a,
                                                     unsigned long long b) {
    return a > b ? a : b;
}

// 320 blocks (32/heatmap) x 256 threads; 32 floats/thread via 8x float4.
// Hot loop: cheap float compare; pack to orderable 64-bit key once at the end.
__global__ void __launch_bounds__(256) argmax_kernel(const float* __restrict__ feat) {
    int hm    = blockIdx.x >> 5;
    int chunk = blockIdx.x & 31;
    const float* heat = feat + HEAT_OFF + (size_t)hm * PLANE;
    int base = chunk * 8192;
    int tid = threadIdx.x;

    float bestv = -__int_as_float(0x7F800000);  // -inf
    int bestidx = 0;
#pragma unroll
    for (int j = 0; j < 8; j++) {
        int e = base + ((j * 256 + tid) << 2);
        float4 v = *reinterpret_cast<const float4*>(heat + e);
        // strict > keeps the FIRST (lowest) index; e strictly increases
        if (v.x > bestv) { bestv = v.x; bestidx = e; }
        if (v.y > bestv) { bestv = v.y; bestidx = e + 1; }
        if (v.z > bestv) { bestv = v.z; bestidx = e + 2; }
        if (v.w > bestv) { bestv = v.w; bestidx = e + 3; }
    }

    // canonical packed key: hi = orderable float, lo = ~idx (lower idx wins ties)
    unsigned long long best =
        ((unsigned long long)fkey(bestv) << 32) |
        (unsigned int)(~(unsigned int)bestidx);

#pragma unroll
    for (int off = 16; off > 0; off >>= 1)
        best = umax64(best, __shfl_xor_sync(0xFFFFFFFFu, best, off));

    __shared__ unsigned long long s[8];
    if ((tid & 31) == 0) s[tid >> 5] = best;
    __syncthreads();
    if (tid < 32) {
        unsigned long long v = (tid < 8) ? s[tid] : 0ULL;
#pragma unroll
        for (int off = 4; off > 0; off >>= 1)
            v = umax64(v, __shfl_xor_sync(0xFFFFFFFFu, v, off));
        if (tid == 0) g_partial[hm][chunk] = v;
    }
}

// grid (NPTS, 64): one block per 2 output rows, 256 threads = one elem each.
// Chain: 32-partial reduce -> sizes -> {saliency || shape rows} -> interp+store.
__global__ void __launch_bounds__(256) compute_kernel(const float* __restrict__ feat,
                                                      float* __restrict__ out) {
    __shared__ float s_v[2][2][32];   // [row-half][y0/y1][x]
    __shared__ int4 s_meta;

    int pt  = blockIdx.x;
    int tid = threadIdx.x;

    // reduce 32 partials in warp 0, resolve idx + sizes
    if (tid < 32) {
        unsigned long long v = g_partial[pt][tid];
#pragma unroll
        for (int off = 16; off > 0; off >>= 1)
            v = umax64(v, __shfl_xor_sync(0xFFFFFFFFu, v, off));
        if (tid == 0) {
            int idx = (int)(~(unsigned int)(v & 0xFFFFFFFFu));
            float hv = fabsf(feat[SIZE_OFF + idx]);
            float wv = fabsf(feat[SIZE_OFF + PLANE + idx]);
            int h = min(max((int)hv, 1), MM);
            int w = min(max((int)wv, 1), MM);
            s_meta = make_int4(idx, h, w, 0);
        }
    }
    __syncthreads();

    int pbase = s_meta.x;
    int h = s_meta.y, w = s_meta.z;
    int py = pbase >> 9;
    int px = pbase & 511;
    float hf = (float)h, wf = (float)w;

    int half = tid >> 7;               // 0 or 1
    int c    = tid & 127;              // column
    int r    = blockIdx.y * 2 + half;  // output row

    float sy = ((float)r + 0.5f) * 32.0f / hf - 0.5f;
    sy = fminf(fmaxf(sy, 0.0f), 31.0f);
    int y0 = (int)floorf(sy);
    int y1 = min(y0 + 1, 31);
    float wy = sy - (float)y0;

    // saliency load: independent of shape gathers -> issued before barrier
    int gr = py - (h >> 1) + r;
    int gc = px - (w >> 1) + c;
    bool valid = (r < h) && (c < w) &&
                 (gr >= 0) && (gr < HH) && (gc >= 0) && (gc < WW);
    float sal = valid ? feat[gr * WW + gc] : 0.0f;

    // shape row gathers (64 scattered loads per half, parallel with sal)
    if (c < 32) {
        s_v[half][0][c] = feat[SHAPE_OFF + (size_t)(y0 * 32 + c) * PLANE + pbase];
    } else if (c < 64) {
        int x = c - 32;
        s_v[half][1][x] = feat[SHAPE_OFF + (size_t)(y1 * 32 + x) * PLANE + pbase];
    }
    __syncthreads();

    float sx = ((float)c + 0.5f) * 32.0f / wf - 0.5f;
    sx = fminf(fmaxf(sx, 0.0f), 31.0f);
    int x0 = (int)floorf(sx);
    int x1 = min(x0 + 1, 31);
    float wx = sx - (float)x0;

    float a0 = s_v[half][0][x0] * (1.0f - wy) + s_v[half][1][x0] * wy;
    float a1 = s_v[half][0][x1] * (1.0f - wy) + s_v[half][1][x1] * wy;
    float v = a0 * (1.0f - wx) + a1 * wx;
    float lv = 1.0f / (1.0f + __expf(-v));

    out[(size_t)pt * (MM * MM) + (size_t)r * MM + c] = valid ? lv * sal : 0.0f;
}

extern "C" void kernel_launch(void* const* d_in, const int* in_sizes, int n_in,
                              void* d_out, int out_size) {
    const float* feat = (const float*)d_in[0];
    float* out = (float*)d_out;
    argmax_kernel<<<NPTS * BLKS_PER_HM, 256>>>(feat);
    dim3 g(NPTS, MM / 2);
    compute_kernel<<<g, 256>>>(feat, out);
}

// round 8
// speedup vs baseline: 1.4686x; 1.0037x over previous
#include <cuda_runtime.h>
#include <math.h>

#define HH 512
#define WW 512
#define PLANE (512*512)
#define SHAPE_OFF (1*PLANE)
#define SIZE_OFF  (1025*PLANE)
#define HEAT_OFF  (1027*PLANE)
#define NPTS 10
#define MM 128
#define BLKS_PER_HM 32

// per-block partial argmax results; every slot written every run -> no init
__device__ unsigned long long g_partial[NPTS][BLKS_PER_HM];

__device__ __forceinline__ unsigned int fkey(float v) {
    unsigned int b = __float_as_uint(v);
    return (b & 0x80000000u) ? ~b : (b | 0x80000000u);
}
__device__ __forceinline__ unsigned long long umax64(unsigned long long a,
                                                     unsigned long long b) {
    return a > b ? a : b;
}

// 320 blocks (32/heatmap) x 256 threads; 32 floats/thread via 8x float4.
// Hot loop: FMNMX tree per quad + rarely-taken update branch (~8 hits/thread).
// Exact first-occurrence index resolved once per thread after the loop.
__global__ void __launch_bounds__(256) argmax_kernel(const float* __restrict__ feat) {
    int hm    = blockIdx.x >> 5;
    int chunk = blockIdx.x & 31;
    const float* heat = feat + HEAT_OFF + (size_t)hm * PLANE;
    int base = chunk * 8192;
    int tid = threadIdx.x;

    float bestv = -__int_as_float(0x7F800000);  // -inf
    int   bestq = base;                          // base index of winning quad
    float4 bq = make_float4(bestv, bestv, bestv, bestv);

#pragma unroll
    for (int j = 0; j < 8; j++) {
        int e = base + ((j * 256 + tid) << 2);
        float4 v = *reinterpret_cast<const float4*>(heat + e);
        float m = fmaxf(fmaxf(v.x, v.y), fmaxf(v.z, v.w));
        // strict > : on ties the EARLIER quad is kept (e strictly increases)
        if (m > bestv) { bestv = m; bestq = e; bq = v; }
    }

    // first element in the winning quad equal to bestv -> global first occurrence
    int off4 = (bq.x == bestv) ? 0 : (bq.y == bestv) ? 1 : (bq.z == bestv) ? 2 : 3;
    int bestidx = bestq + off4;

    unsigned long long best =
        ((unsigned long long)fkey(bestv) << 32) |
        (unsigned int)(~(unsigned int)bestidx);

#pragma unroll
    for (int off = 16; off > 0; off >>= 1)
        best = umax64(best, __shfl_xor_sync(0xFFFFFFFFu, best, off));

    __shared__ unsigned long long s[8];
    if ((tid & 31) == 0) s[tid >> 5] = best;
    __syncthreads();
    if (tid < 32) {
        unsigned long long v = (tid < 8) ? s[tid] : 0ULL;
#pragma unroll
        for (int off = 4; off > 0; off >>= 1)
            v = umax64(v, __shfl_xor_sync(0xFFFFFFFFu, v, off));
        if (tid == 0) g_partial[hm][chunk] = v;
    }
}

// grid (NPTS, 64): one block per 2 output rows, 256 threads = one elem each.
// Chain: 32-partial reduce -> sizes -> {saliency || shape rows} -> interp+store.
__global__ void __launch_bounds__(256) compute_kernel(const float* __restrict__ feat,
                                                      float* __restrict__ out) {
    __shared__ float s_v[2][2][32];   // [row-half][y0/y1][x]
    __shared__ int4 s_meta;

    int pt  = blockIdx.x;
    int tid = threadIdx.x;

    // reduce 32 partials in warp 0, resolve idx + sizes
    if (tid < 32) {
        unsigned long long v = g_partial[pt][tid];
#pragma unroll
        for (int off = 16; off > 0; off >>= 1)
            v = umax64(v, __shfl_xor_sync(0xFFFFFFFFu, v, off));
        if (tid == 0) {
            int idx = (int)(~(unsigned int)(v & 0xFFFFFFFFu));
            float hv = fabsf(feat[SIZE_OFF + idx]);
            float wv = fabsf(feat[SIZE_OFF + PLANE + idx]);
            int h = min(max((int)hv, 1), MM);
            int w = min(max((int)wv, 1), MM);
            s_meta = make_int4(idx, h, w, 0);
        }
    }
    __syncthreads();

    int pbase = s_meta.x;
    int h = s_meta.y, w = s_meta.z;
    int py = pbase >> 9;
    int px = pbase & 511;
    float hf = (float)h, wf = (float)w;

    int half = tid >> 7;               // 0 or 1
    int c    = tid & 127;              // column
    int r    = blockIdx.y * 2 + half;  // output row

    float sy = ((float)r + 0.5f) * 32.0f / hf - 0.5f;
    sy = fminf(fmaxf(sy, 0.0f), 31.0f);
    int y0 = (int)floorf(sy);
    int y1 = min(y0 + 1, 31);
    float wy = sy - (float)y0;

    // saliency load: independent of shape gathers -> issued before barrier
    int gr = py - (h >> 1) + r;
    int gc = px - (w >> 1) + c;
    bool valid = (r < h) && (c < w) &&
                 (gr >= 0) && (gr < HH) && (gc >= 0) && (gc < WW);
    float sal = valid ? feat[gr * WW + gc] : 0.0f;

    // shape row gathers (64 scattered loads per half, parallel with sal)
    if (c < 32) {
        s_v[half][0][c] = feat[SHAPE_OFF + (size_t)(y0 * 32 + c) * PLANE + pbase];
    } else if (c < 64) {
        int x = c - 32;
        s_v[half][1][x] = feat[SHAPE_OFF + (size_t)(y1 * 32 + x) * PLANE + pbase];
    }
    __syncthreads();

    float sx = ((float)c + 0.5f) * 32.0f / wf - 0.5f;
    sx = fminf(fmaxf(sx, 0.0f), 31.0f);
    int x0 = (int)floorf(sx);
    int x1 = min(x0 + 1, 31);
    float wx = sx - (float)x0;

    float a0 = s_v[half][0][x0] * (1.0f - wy) + s_v[half][1][x0] * wy;
    float a1 = s_v[half][0][x1] * (1.0f - wy) + s_v[half][1][x1] * wy;
    float v = a0 * (1.0f - wx) + a1 * wx;
    float lv = 1.0f / (1.0f + __expf(-v));

    out[(size_t)pt * (MM * MM) + (size_t)r * MM + c] = valid ? lv * sal : 0.0f;
}

extern "C" void kernel_launch(void* const* d_in, const int* in_sizes, int n_in,
                              void* d_out, int out_size) {
    const float* feat = (const float*)d_in[0];
    float* out = (float*)d_out;
    argmax_kernel<<<NPTS * BLKS_PER_HM, 256>>>(feat);
    dim3 g(NPTS, MM / 2);
    compute_kernel<<<g, 256>>>(feat, out);
}